// round 3
// baseline (speedup 1.0000x reference)
#include <cuda_runtime.h>

// Router: logits = x[8192,4096] @ kernel[4096,64]; top-8 per token; softmax over top-8.
// out (fp32): [0 .. T*8) = normalized weights, [T*8 .. 2*T*8) = expert indices (as float)
//
// Accumulation scheme: split-K(8) — 8 contiguous 512-element K-slabs, each a fresh
// sequential fp32 accumulator, folded into the master sequentially in slab order.
// Chosen to replicate the reference's (cublas splitK) rounding so near-tie top-k
// decisions correlate.

#define T_TOK 8192
#define D_DIM 4096
#define E_EXP 64
#define TT    64     // tokens per block
#define KC    64     // K-chunk staged through smem
#define SLAB_CHUNKS 8   // 8 chunks of 64 = 512-K slab per partial
#define XS_PAD 68

typedef unsigned long long u64;

__device__ __forceinline__ u64 ffma2(u64 a, u64 b, u64 c) {
    u64 d;
    asm("fma.rn.f32x2 %0, %1, %2, %3;" : "=l"(d) : "l"(a), "l"(b), "l"(c));
    return d;
}
__device__ __forceinline__ u64 padd(u64 a, u64 b) {
    u64 d;
    asm("add.rn.f32x2 %0, %1, %2;" : "=l"(d) : "l"(a), "l"(b));
    return d;
}
__device__ __forceinline__ u64 bcast2(float x) {
    u64 r;
    asm("mov.b64 %0, {%1, %1};" : "=l"(r) : "f"(x));
    return r;
}

__global__ __launch_bounds__(128) void router_kernel(
    const float* __restrict__ x,
    const float* __restrict__ ker,
    float* __restrict__ out,
    int half)
{
    __shared__ float xs[TT * XS_PAD];
    __shared__ union {
        float ks[KC * E_EXP];
        float lg[TT * E_EXP];
    } u;

    const int tid = threadIdx.x;
    const int tx  = tid & 7;
    const int ty  = tid >> 3;
    const int e0  = tx * 8;
    const int tb  = blockIdx.x * TT;

    // master accumulators (sum of slab partials) + current slab partial
    u64 acc[4][4], pacc[4][4];
#pragma unroll
    for (int i = 0; i < 4; i++)
#pragma unroll
        for (int j = 0; j < 4; j++) { acc[i][j] = 0ull; pacc[i][j] = 0ull; }

    const int nChunks = D_DIM / KC;   // 64
    for (int c = 0; c < nChunks; c++) {
        __syncthreads();

        // ---- load x chunk: 64 tokens x 64 d, coalesced float4 ----
        {
            const float4* xg = reinterpret_cast<const float4*>(x);
#pragma unroll
            for (int j = 0; j < 8; j++) {
                int f  = j * 128 + tid;
                int d4 = f & 15;
                int t  = f >> 4;
                float4 v = xg[(size_t)(tb + t) * (D_DIM / 4) + c * (KC / 4) + d4];
                *reinterpret_cast<float4*>(&xs[t * XS_PAD + d4 * 4]) = v;
            }
        }
        // ---- load k chunk: 64 d x 64 e ----
        {
            const float4* kg = reinterpret_cast<const float4*>(ker);
#pragma unroll
            for (int j = 0; j < 8; j++) {
                int f  = j * 128 + tid;
                int e4 = f & 15;
                int dk = f >> 4;
                float4 v = kg[(size_t)(c * KC + dk) * (E_EXP / 4) + e4];
                *reinterpret_cast<float4*>(&u.ks[dk * E_EXP + e4 * 4]) = v;
            }
        }
        __syncthreads();

        // ---- compute: sequential fp32 into current slab partial ----
#pragma unroll 8
        for (int kk = 0; kk < KC; kk++) {
            ulonglong2 ka = *reinterpret_cast<const ulonglong2*>(&u.ks[kk * E_EXP + e0]);
            ulonglong2 kb = *reinterpret_cast<const ulonglong2*>(&u.ks[kk * E_EXP + e0 + 4]);
#pragma unroll
            for (int i = 0; i < 4; i++) {
                u64 xp = bcast2(xs[(ty + 16 * i) * XS_PAD + kk]);
                pacc[i][0] = ffma2(xp, ka.x, pacc[i][0]);
                pacc[i][1] = ffma2(xp, ka.y, pacc[i][1]);
                pacc[i][2] = ffma2(xp, kb.x, pacc[i][2]);
                pacc[i][3] = ffma2(xp, kb.y, pacc[i][3]);
            }
        }

        // ---- end of 512-K slab: fold partial into master (ordered), reset partial ----
        if ((c & (SLAB_CHUNKS - 1)) == (SLAB_CHUNKS - 1)) {
#pragma unroll
            for (int i = 0; i < 4; i++)
#pragma unroll
                for (int j = 0; j < 4; j++) {
                    acc[i][j]  = padd(acc[i][j], pacc[i][j]);
                    pacc[i][j] = 0ull;
                }
        }
    }

    __syncthreads();

    // ---- write logits to smem ----
#pragma unroll
    for (int i = 0; i < 4; i++) {
        int t = ty + 16 * i;
#pragma unroll
        for (int j = 0; j < 4; j++) {
            float2 p = *reinterpret_cast<float2*>(&acc[i][j]);
            *reinterpret_cast<float2*>(&u.lg[t * E_EXP + e0 + 2 * j]) = p;
        }
    }
    __syncthreads();

    // ---- top-8 + softmax: one warp per 16 tokens ----
    const int w    = tid >> 5;
    const int lane = tid & 31;
    const unsigned FULL = 0xffffffffu;

    for (int s = 0; s < 16; s++) {
        int t = w * 16 + s;
        float v0 = u.lg[t * E_EXP + lane];
        float v1 = u.lg[t * E_EXP + 32 + lane];

        float vals[8];
        int   inds[8];
#pragma unroll
        for (int k = 0; k < 8; k++) {
            float bv; int bi;
            if (v0 >= v1) { bv = v0; bi = lane; }
            else          { bv = v1; bi = lane + 32; }
#pragma unroll
            for (int off = 16; off > 0; off >>= 1) {
                float ov = __shfl_xor_sync(FULL, bv, off);
                int   oi = __shfl_xor_sync(FULL, bi, off);
                if (ov > bv || (ov == bv && oi < bi)) { bv = ov; bi = oi; }
            }
            vals[k] = bv;
            inds[k] = bi;
            if (bi == lane)           v0 = -3.4e38f;
            else if (bi == lane + 32) v1 = -3.4e38f;
        }

        if (lane == 0) {
            float m = vals[0];
            float ws[8];
            float ssum = 0.0f;
#pragma unroll
            for (int k = 0; k < 8; k++) { ws[k] = expf(vals[k] - m); ssum += ws[k]; }
            float r = 1.0f / ssum;
            int tg = tb + t;
#pragma unroll
            for (int k = 0; k < 8; k++) {
                out[tg * 8 + k]        = ws[k] * r;
                out[half + tg * 8 + k] = (float)inds[k];
            }
        }
    }
}

extern "C" void kernel_launch(void* const* d_in, const int* in_sizes, int n_in,
                              void* d_out, int out_size) {
    const float* x   = (const float*)d_in[0];
    const float* ker = (const float*)d_in[1];
    float* out = (float*)d_out;
    int half = out_size / 2;

    router_kernel<<<T_TOK / TT, 128>>>(x, ker, out, half);
}

// round 4
// speedup vs baseline: 1.0211x; 1.0211x over previous
#include <cuda_runtime.h>
#include <cstdint>

// Router: logits = x[8192,4096] @ kernel[4096,64]; top-8 per token; softmax over top-8.
// out (fp32): [0 .. T*8) = weights, [T*8 .. 2*T*8) = expert indices (as float)
//
// Accumulation: split-K(8) — fresh sequential fp32 partial per 512-K slab, folded
// into master in slab order (replicates reference/cublas rounding; DO NOT CHANGE).
// Pipeline: cp.async 2-stage double buffer; 256 CTAs x 128 thr, 2 CTAs/SM.

#define T_TOK 8192
#define D_DIM 4096
#define E_EXP 64
#define TT    32      // tokens per block
#define KC    64      // K-chunk per stage
#define SLAB_CHUNKS 8 // 512-K slab = 8 chunks

typedef unsigned long long u64;

__device__ __forceinline__ u64 ffma2(u64 a, u64 b, u64 c) {
    u64 d;
    asm("fma.rn.f32x2 %0, %1, %2, %3;" : "=l"(d) : "l"(a), "l"(b), "l"(c));
    return d;
}
__device__ __forceinline__ u64 padd(u64 a, u64 b) {
    u64 d;
    asm("add.rn.f32x2 %0, %1, %2;" : "=l"(d) : "l"(a), "l"(b));
    return d;
}
__device__ __forceinline__ u64 bcast2(float x) {
    u64 r;
    asm("mov.b64 %0, {%1, %1};" : "=l"(r) : "f"(x));
    return r;
}
__device__ __forceinline__ void cp16(uint32_t smem_addr, const void* gptr) {
    asm volatile("cp.async.cg.shared.global [%0], [%1], 16;" :: "r"(smem_addr), "l"(gptr));
}
__device__ __forceinline__ void cp_commit() { asm volatile("cp.async.commit_group;"); }
__device__ __forceinline__ void cp_wait1()  { asm volatile("cp.async.wait_group 1;"); }
__device__ __forceinline__ void cp_wait0()  { asm volatile("cp.async.wait_group 0;"); }

// smem layout (floats): xs stage0 [0,2048), xs stage1 [2048,4096),
//                       ks stage0 [4096,8192), ks stage1 [8192,12288)
// epilogue: logits [0, 2048) overlaying xs.
__global__ __launch_bounds__(128, 2) void router_kernel(
    const float* __restrict__ x,
    const float* __restrict__ ker,
    float* __restrict__ out,
    int half)
{
    __shared__ float sm[2 * TT * KC + 2 * KC * E_EXP];   // 12288 floats = 48KB

    const int tid = threadIdx.x;
    const int tx  = tid & 7;        // e-group: e0 = tx*8
    const int ty  = tid >> 3;       // 0..15 -> rows ty, ty+16
    const int e0  = tx * 8;
    const int tb  = blockIdx.x * TT;
    const int sw  = ty & 3;         // x-tile chunk swizzle key (same for both rows)

    const uint32_t smb = (uint32_t)__cvta_generic_to_shared(sm);

    // master + slab-partial accumulators: 2 t-rows x 4 e-pairs (packed f32x2)
    u64 acc[2][4], pacc[2][4];
#pragma unroll
    for (int i = 0; i < 2; i++)
#pragma unroll
        for (int j = 0; j < 4; j++) { acc[i][j] = 0ull; pacc[i][j] = 0ull; }

    // ---- async chunk loader: x tile (swizzled 16B chunks) + k tile ----
    auto load_chunk = [&](int c, int b) {
#pragma unroll
        for (int j = 0; j < 4; j++) {                 // x: 512 float4s / 128 thr
            int f  = j * 128 + tid;
            int d4 = f & 15;                          // chunk within row
            int t  = f >> 4;                          // 0..31
            uint32_t dst = smb + ((b * TT * KC) + t * KC + ((d4 ^ (t & 3)) << 2)) * 4;
            const float* src = x + (size_t)(tb + t) * D_DIM + c * KC + d4 * 4;
            cp16(dst, src);
        }
#pragma unroll
        for (int j = 0; j < 8; j++) {                 // k: 1024 float4s / 128 thr
            int f  = j * 128 + tid;
            int e4 = f & 15;
            int dk = f >> 4;
            uint32_t dst = smb + (2 * TT * KC + b * KC * E_EXP + dk * E_EXP + e4 * 4) * 4;
            const float* src = ker + (size_t)(c * KC + dk) * E_EXP + e4 * 4;
            cp16(dst, src);
        }
        cp_commit();
    };

    load_chunk(0, 0);

    const int nChunks = D_DIM / KC;   // 64
    for (int c = 0; c < nChunks; c++) {
        if (c < nChunks - 1) { load_chunk(c + 1, (c + 1) & 1); cp_wait1(); }
        else                 { cp_wait0(); }
        __syncthreads();

        const int b = c & 1;
        const float* xr0 = sm + b * TT * KC + ty * KC;
        const float* xr1 = xr0 + 16 * KC;
        const float* kb_ = sm + 2 * TT * KC + b * KC * E_EXP;

#pragma unroll 4
        for (int c4 = 0; c4 < KC / 4; c4++) {
            const int ch = ((c4 ^ sw) << 2);
            float4 xa = *reinterpret_cast<const float4*>(xr0 + ch);
            float4 xb = *reinterpret_cast<const float4*>(xr1 + ch);
#pragma unroll
            for (int q = 0; q < 4; q++) {
                const int kk = c4 * 4 + q;
                ulonglong2 ka = *reinterpret_cast<const ulonglong2*>(kb_ + kk * E_EXP + e0);
                ulonglong2 kc = *reinterpret_cast<const ulonglong2*>(kb_ + kk * E_EXP + e0 + 4);
                float fa = (q == 0) ? xa.x : (q == 1) ? xa.y : (q == 2) ? xa.z : xa.w;
                float fb = (q == 0) ? xb.x : (q == 1) ? xb.y : (q == 2) ? xb.z : xb.w;
                u64 xp0 = bcast2(fa);
                u64 xp1 = bcast2(fb);
                pacc[0][0] = ffma2(xp0, ka.x, pacc[0][0]);
                pacc[0][1] = ffma2(xp0, ka.y, pacc[0][1]);
                pacc[0][2] = ffma2(xp0, kc.x, pacc[0][2]);
                pacc[0][3] = ffma2(xp0, kc.y, pacc[0][3]);
                pacc[1][0] = ffma2(xp1, ka.x, pacc[1][0]);
                pacc[1][1] = ffma2(xp1, ka.y, pacc[1][1]);
                pacc[1][2] = ffma2(xp1, kc.x, pacc[1][2]);
                pacc[1][3] = ffma2(xp1, kc.y, pacc[1][3]);
            }
        }

        if ((c & (SLAB_CHUNKS - 1)) == (SLAB_CHUNKS - 1)) {
#pragma unroll
            for (int i = 0; i < 2; i++)
#pragma unroll
                for (int j = 0; j < 4; j++) {
                    acc[i][j]  = padd(acc[i][j], pacc[i][j]);
                    pacc[i][j] = 0ull;
                }
        }
        __syncthreads();   // protect buffer b before it is refilled at iter c+1
    }

    // ---- write logits to smem (overlay xs region) ----
    float* lg = sm;
#pragma unroll
    for (int i = 0; i < 2; i++) {
        int t = ty + 16 * i;
#pragma unroll
        for (int j = 0; j < 4; j++) {
            float2 p = *reinterpret_cast<float2*>(&acc[i][j]);
            *reinterpret_cast<float2*>(&lg[t * E_EXP + e0 + 2 * j]) = p;
        }
    }
    __syncthreads();

    // ---- top-8 + softmax: one warp per 8 tokens ----
    const int w    = tid >> 5;
    const int lane = tid & 31;
    const unsigned FULL = 0xffffffffu;

    for (int s = 0; s < 8; s++) {
        int t = w * 8 + s;
        float v0 = lg[t * E_EXP + lane];
        float v1 = lg[t * E_EXP + 32 + lane];

        float vals[8];
        int   inds[8];
#pragma unroll
        for (int k = 0; k < 8; k++) {
            float bv; int bi;
            if (v0 >= v1) { bv = v0; bi = lane; }
            else          { bv = v1; bi = lane + 32; }
#pragma unroll
            for (int off = 16; off > 0; off >>= 1) {
                float ov = __shfl_xor_sync(FULL, bv, off);
                int   oi = __shfl_xor_sync(FULL, bi, off);
                if (ov > bv || (ov == bv && oi < bi)) { bv = ov; bi = oi; }
            }
            vals[k] = bv;
            inds[k] = bi;
            if (bi == lane)           v0 = -3.4e38f;
            else if (bi == lane + 32) v1 = -3.4e38f;
        }

        if (lane == 0) {
            float m = vals[0];
            float ws[8];
            float ssum = 0.0f;
#pragma unroll
            for (int k = 0; k < 8; k++) { ws[k] = expf(vals[k] - m); ssum += ws[k]; }
            float r = 1.0f / ssum;
            int tg = tb + t;
#pragma unroll
            for (int k = 0; k < 8; k++) {
                out[tg * 8 + k]        = ws[k] * r;
                out[half + tg * 8 + k] = (float)inds[k];
            }
        }
    }
}

extern "C" void kernel_launch(void* const* d_in, const int* in_sizes, int n_in,
                              void* d_out, int out_size) {
    const float* x   = (const float*)d_in[0];
    const float* ker = (const float*)d_in[1];
    float* out = (float*)d_out;
    int half = out_size / 2;

    router_kernel<<<T_TOK / TT, 128>>>(x, ker, out, half);
}

// round 5
// speedup vs baseline: 1.5684x; 1.5360x over previous
#include <cuda_runtime.h>
#include <cstdint>

// Router: logits = x[8192,4096] @ kernel[4096,64]; top-8 per token; softmax over top-8.
// out (fp32): [0 .. T*8) = weights, [T*8 .. 2*T*8) = expert indices (as float)
//
// Accumulation: split-K(8) — fresh sequential fp32 partial per 512-K slab, folded
// into master in slab order (replicates reference rounding; DO NOT CHANGE).
// 128 CTAs x 256 thr, 3-stage cp.async pipeline, conflict-free phase-split k tile.

#define T_TOK 8192
#define D_DIM 4096
#define E_EXP 64
#define TT    64      // tokens per block
#define KC    64      // K-chunk per stage
#define SLAB_CHUNKS 8 // 512-K slab = 8 chunks
#define LDK   72      // k-tile row stride (floats), phase-split layout
#define XTILE (TT * KC)          // 4096 floats
#define KTILE (KC * LDK)         // 4608 floats
#define STAGE (XTILE + KTILE)    // 8704 floats per stage
#define NSTG  3

typedef unsigned long long u64;

__device__ __forceinline__ u64 ffma2(u64 a, u64 b, u64 c) {
    u64 d;
    asm("fma.rn.f32x2 %0, %1, %2, %3;" : "=l"(d) : "l"(a), "l"(b), "l"(c));
    return d;
}
__device__ __forceinline__ u64 padd(u64 a, u64 b) {
    u64 d;
    asm("add.rn.f32x2 %0, %1, %2;" : "=l"(d) : "l"(a), "l"(b));
    return d;
}
__device__ __forceinline__ u64 bcast2(float x) {
    u64 r;
    asm("mov.b64 %0, {%1, %1};" : "=l"(r) : "f"(x));
    return r;
}
__device__ __forceinline__ void cp16(uint32_t smem_addr, const void* gptr) {
    asm volatile("cp.async.cg.shared.global [%0], [%1], 16;" :: "r"(smem_addr), "l"(gptr));
}
__device__ __forceinline__ void cp_commit() { asm volatile("cp.async.commit_group;"); }
__device__ __forceinline__ void cp_wait1()  { asm volatile("cp.async.wait_group 1;"); }
__device__ __forceinline__ void cp_wait0()  { asm volatile("cp.async.wait_group 0;"); }

extern __shared__ float sm[];   // NSTG * STAGE floats

__global__ __launch_bounds__(256, 1) void router_kernel(
    const float* __restrict__ x,
    const float* __restrict__ ker,
    float* __restrict__ out,
    int half)
{
    const int tid = threadIdx.x;
    const int tx  = tid & 7;        // e-group: e0 = tx*8
    const int ty  = tid >> 3;       // 0..31 -> rows ty, ty+32
    const int e0  = tx * 8;
    const int koff = e0 + ((tx >= 4) ? 4 : 0);   // phase-split k offset
    const int tb  = blockIdx.x * TT;
    const int sw  = ty & 3;         // x chunk swizzle key (rows ty and ty+32 share it)

    const uint32_t smb = (uint32_t)__cvta_generic_to_shared(sm);

    // master + slab-partial accumulators: 2 t-rows x 4 e-pairs (packed f32x2)
    u64 acc[2][4], pacc[2][4];
#pragma unroll
    for (int i = 0; i < 2; i++)
#pragma unroll
        for (int j = 0; j < 4; j++) { acc[i][j] = 0ull; pacc[i][j] = 0ull; }

    // ---- async chunk loader ----
    auto load_chunk = [&](int c, int s) {
        uint32_t base = smb + (uint32_t)(s * STAGE) * 4u;
#pragma unroll
        for (int j = 0; j < 4; j++) {                 // x: 1024 float4s / 256 thr
            int f  = j * 256 + tid;
            int d4 = f & 15;                          // 16B chunk within row
            int t  = f >> 4;                          // 0..63
            uint32_t dst = base + (uint32_t)(t * KC + ((d4 ^ (t & 3)) << 2)) * 4u;
            const float* src = x + (size_t)(tb + t) * D_DIM + c * KC + d4 * 4;
            cp16(dst, src);
        }
#pragma unroll
        for (int j = 0; j < 4; j++) {                 // k: 1024 float4s / 256 thr
            int f  = j * 256 + tid;
            int e4 = f & 15;                          // 16B chunk within kk-row
            int dk = f >> 4;                          // 0..63
            int ofs = e4 * 4 + ((e4 >= 8) ? 4 : 0);   // phase-split
            uint32_t dst = base + (uint32_t)(XTILE + dk * LDK + ofs) * 4u;
            const float* src = ker + (size_t)(c * KC + dk) * E_EXP + e4 * 4;
            cp16(dst, src);
        }
        cp_commit();
    };

    load_chunk(0, 0);
    load_chunk(1, 1);

    const int nChunks = D_DIM / KC;   // 64
    for (int c = 0; c < nChunks; c++) {
        if (c == nChunks - 1) cp_wait0(); else cp_wait1();
        __syncthreads();                       // stage c visible to all; chunk c-1 reads done

        if (c + 2 < nChunks) load_chunk(c + 2, (c + 2) % NSTG);

        const float* sb  = sm + (c % NSTG) * STAGE;
        const float* xr0 = sb + ty * KC;
        const float* xr1 = xr0 + 32 * KC;
        const float* kb_ = sb + XTILE;

#pragma unroll 4
        for (int c4 = 0; c4 < KC / 4; c4++) {
            const int ch = ((c4 ^ sw) << 2);
            float4 xa = *reinterpret_cast<const float4*>(xr0 + ch);
            float4 xb = *reinterpret_cast<const float4*>(xr1 + ch);
#pragma unroll
            for (int q = 0; q < 4; q++) {
                const int kk = c4 * 4 + q;
                ulonglong2 ka = *reinterpret_cast<const ulonglong2*>(kb_ + kk * LDK + koff);
                ulonglong2 kc = *reinterpret_cast<const ulonglong2*>(kb_ + kk * LDK + koff + 4);
                float fa = (q == 0) ? xa.x : (q == 1) ? xa.y : (q == 2) ? xa.z : xa.w;
                float fb = (q == 0) ? xb.x : (q == 1) ? xb.y : (q == 2) ? xb.z : xb.w;
                u64 xp0 = bcast2(fa);
                u64 xp1 = bcast2(fb);
                pacc[0][0] = ffma2(xp0, ka.x, pacc[0][0]);
                pacc[0][1] = ffma2(xp0, ka.y, pacc[0][1]);
                pacc[0][2] = ffma2(xp0, kc.x, pacc[0][2]);
                pacc[0][3] = ffma2(xp0, kc.y, pacc[0][3]);
                pacc[1][0] = ffma2(xp1, ka.x, pacc[1][0]);
                pacc[1][1] = ffma2(xp1, ka.y, pacc[1][1]);
                pacc[1][2] = ffma2(xp1, kc.x, pacc[1][2]);
                pacc[1][3] = ffma2(xp1, kc.y, pacc[1][3]);
            }
        }

        if ((c & (SLAB_CHUNKS - 1)) == (SLAB_CHUNKS - 1)) {
#pragma unroll
            for (int i = 0; i < 2; i++)
#pragma unroll
                for (int j = 0; j < 4; j++) {
                    acc[i][j]  = padd(acc[i][j], pacc[i][j]);
                    pacc[i][j] = 0ull;
                }
        }
    }

    __syncthreads();

    // ---- write logits to smem (overlay stage 0) ----
    float* lg = sm;
#pragma unroll
    for (int i = 0; i < 2; i++) {
        int t = ty + 32 * i;
#pragma unroll
        for (int j = 0; j < 4; j++) {
            float2 p = *reinterpret_cast<float2*>(&acc[i][j]);
            *reinterpret_cast<float2*>(&lg[t * E_EXP + e0 + 2 * j]) = p;
        }
    }
    __syncthreads();

    // ---- top-8 + softmax: one warp per 8 tokens ----
    const int w    = tid >> 5;
    const int lane = tid & 31;
    const unsigned FULL = 0xffffffffu;

    for (int s = 0; s < 8; s++) {
        int t = w * 8 + s;
        float v0 = lg[t * E_EXP + lane];
        float v1 = lg[t * E_EXP + 32 + lane];

        float vals[8];
        int   inds[8];
#pragma unroll
        for (int k = 0; k < 8; k++) {
            float bv; int bi;
            if (v0 >= v1) { bv = v0; bi = lane; }
            else          { bv = v1; bi = lane + 32; }
#pragma unroll
            for (int off = 16; off > 0; off >>= 1) {
                float ov = __shfl_xor_sync(FULL, bv, off);
                int   oi = __shfl_xor_sync(FULL, bi, off);
                if (ov > bv || (ov == bv && oi < bi)) { bv = ov; bi = oi; }
            }
            vals[k] = bv;
            inds[k] = bi;
            if (bi == lane)           v0 = -3.4e38f;
            else if (bi == lane + 32) v1 = -3.4e38f;
        }

        if (lane == 0) {
            float m = vals[0];
            float ws[8];
            float ssum = 0.0f;
#pragma unroll
            for (int k = 0; k < 8; k++) { ws[k] = expf(vals[k] - m); ssum += ws[k]; }
            float r = 1.0f / ssum;
            int tg = tb + t;
#pragma unroll
            for (int k = 0; k < 8; k++) {
                out[tg * 8 + k]        = ws[k] * r;
                out[half + tg * 8 + k] = (float)inds[k];
            }
        }
    }
}

extern "C" void kernel_launch(void* const* d_in, const int* in_sizes, int n_in,
                              void* d_out, int out_size) {
    const float* x   = (const float*)d_in[0];
    const float* ker = (const float*)d_in[1];
    float* out = (float*)d_out;
    int half = out_size / 2;

    static bool attr_set = false;
    if (!attr_set) {
        cudaFuncSetAttribute(router_kernel,
                             cudaFuncAttributeMaxDynamicSharedMemorySize,
                             NSTG * STAGE * sizeof(float));
        attr_set = true;
    }
    router_kernel<<<T_TOK / TT, 256, NSTG * STAGE * sizeof(float)>>>(x, ker, out, half);
}

// round 6
// speedup vs baseline: 2.7075x; 1.7264x over previous
#include <cuda_runtime.h>
#include <cstdint>

// Router: logits = x[8192,4096] @ kernel[4096,64]; top-8 per token; softmax over top-8.
// out (fp32): [0 .. T*8) = weights, [T*8 .. 2*T*8) = expert indices (as float)
//
// Physical split-K(8): pass1 computes per-slab partials (sequential fp32, ascending kk
// within the 512-K slab — identical rounding to the reference); pass2 folds partials
// in slab order and does top-8 + softmax. DO NOT change the accumulation order.

#define T_TOK 8192
#define D_DIM 4096
#define E_EXP 64
#define NSLAB 8
#define SLABK 512
#define TT    64      // tokens per pass1 CTA
#define KC    32      // K-chunk per stage
#define LDK   72      // k-tile row stride (floats), phase-split
#define XTILE (TT * KC)          // 2048 floats
#define KTILE (KC * LDK)         // 2304 floats
#define STAGE (XTILE + KTILE)    // 4352 floats

typedef unsigned long long u64;

__device__ float g_partial[NSLAB * T_TOK * E_EXP];   // 16.8 MB scratch

__device__ __forceinline__ u64 ffma2(u64 a, u64 b, u64 c) {
    u64 d;
    asm("fma.rn.f32x2 %0, %1, %2, %3;" : "=l"(d) : "l"(a), "l"(b), "l"(c));
    return d;
}
__device__ __forceinline__ u64 bcast2(float x) {
    u64 r;
    asm("mov.b64 %0, {%1, %1};" : "=l"(r) : "f"(x));
    return r;
}
__device__ __forceinline__ void cp16(uint32_t smem_addr, const void* gptr) {
    asm volatile("cp.async.cg.shared.global [%0], [%1], 16;" :: "r"(smem_addr), "l"(gptr));
}
__device__ __forceinline__ void cp_commit() { asm volatile("cp.async.commit_group;"); }
__device__ __forceinline__ void cp_wait1()  { asm volatile("cp.async.wait_group 1;"); }
__device__ __forceinline__ void cp_wait0()  { asm volatile("cp.async.wait_group 0;"); }

// ============================ PASS 1: slab GEMM ============================
// grid (128 t-blocks, 8 slabs), 64 threads. Thread tile: 8 rows x 8 experts.
__global__ __launch_bounds__(64, 6) void slab_gemm_kernel(
    const float* __restrict__ x,
    const float* __restrict__ ker)
{
    __shared__ float sm[2 * STAGE];   // 34.8 KB

    const int tid  = threadIdx.x;
    const int tx   = tid & 7;            // e-group: e0 = tx*8
    const int ty   = tid >> 3;           // 0..7 -> rows ty + 8*i
    const int e0   = tx * 8;
    const int koff = e0 + ((tx >= 4) ? 4 : 0);
    const int tb   = blockIdx.x * TT;
    const int k0   = blockIdx.y * SLABK;

    const uint32_t smb = (uint32_t)__cvta_generic_to_shared(sm);

    // acc: 8 rows x 4 e-pairs (packed f32x2) — plain sequential fp32 over this slab
    u64 acc[8][4];
#pragma unroll
    for (int i = 0; i < 8; i++)
#pragma unroll
        for (int j = 0; j < 4; j++) acc[i][j] = 0ull;

    auto load_chunk = [&](int c, int s) {
        uint32_t base = smb + (uint32_t)(s * STAGE) * 4u;
        // x: 64 rows x 32 fl = 512 float4 / 64 thr = 8 each
#pragma unroll
        for (int j = 0; j < 8; j++) {
            int t = 8 * j + ty;                       // row
            uint32_t dst = base + (uint32_t)(t * KC + ((tx ^ ty) << 2)) * 4u;
            const float* src = x + (size_t)(tb + t) * D_DIM + k0 + c * KC + tx * 4;
            cp16(dst, src);
        }
        // k: 32 kk x 64 e = 512 float4 / 64 thr = 8 each (phase-split rows)
        int e4 = tid & 15;
        int ofs = e4 * 4 + ((e4 >= 8) ? 4 : 0);
#pragma unroll
        for (int j = 0; j < 8; j++) {
            int dk = 4 * j + (tid >> 4);
            uint32_t dst = base + (uint32_t)(XTILE + dk * LDK + ofs) * 4u;
            const float* src = ker + (size_t)(k0 + c * KC + dk) * E_EXP + e4 * 4;
            cp16(dst, src);
        }
        cp_commit();
    };

    load_chunk(0, 0);
    load_chunk(1, 1);

    const int nChunks = SLABK / KC;   // 16
    for (int c = 0; c < nChunks; c++) {
        if (c == nChunks - 1) cp_wait0(); else cp_wait1();
        __syncthreads();

        const int b = c & 1;
        const float* xb_ = sm + b * STAGE;
        const float* kb_ = sm + b * STAGE + XTILE;

#pragma unroll
        for (int c4 = 0; c4 < KC / 4; c4++) {
            const int ch = ((c4 ^ ty) << 2);
            float4 xv[8];
#pragma unroll
            for (int i = 0; i < 8; i++)
                xv[i] = *reinterpret_cast<const float4*>(xb_ + (ty + 8 * i) * KC + ch);
#pragma unroll
            for (int q = 0; q < 4; q++) {
                const int kk = c4 * 4 + q;
                ulonglong2 ka = *reinterpret_cast<const ulonglong2*>(kb_ + kk * LDK + koff);
                ulonglong2 kc = *reinterpret_cast<const ulonglong2*>(kb_ + kk * LDK + koff + 4);
#pragma unroll
                for (int i = 0; i < 8; i++) {
                    float fx = (q == 0) ? xv[i].x : (q == 1) ? xv[i].y
                             : (q == 2) ? xv[i].z : xv[i].w;
                    u64 xp = bcast2(fx);
                    acc[i][0] = ffma2(xp, ka.x, acc[i][0]);
                    acc[i][1] = ffma2(xp, ka.y, acc[i][1]);
                    acc[i][2] = ffma2(xp, kc.x, acc[i][2]);
                    acc[i][3] = ffma2(xp, kc.y, acc[i][3]);
                }
            }
        }
        __syncthreads();   // all reads of buffer b done before refill
        if (c + 2 < nChunks) load_chunk(c + 2, b);
    }

    // write slab partial: [slab][t][e]
    float* pout = g_partial + (size_t)blockIdx.y * T_TOK * E_EXP;
#pragma unroll
    for (int i = 0; i < 8; i++) {
        int t = tb + ty + 8 * i;
        float* row = pout + (size_t)t * E_EXP + e0;
        *reinterpret_cast<float4*>(row)     = *reinterpret_cast<float4*>(&acc[i][0]);
        *reinterpret_cast<float4*>(row + 4) = *reinterpret_cast<float4*>(&acc[i][2]);
    }
}

// ====================== PASS 2: fold + top-8 + softmax ======================
__global__ __launch_bounds__(256) void fold_topk_kernel(
    float* __restrict__ out,
    int half)
{
    __shared__ float lg[TT * E_EXP];   // 16 KB

    const int tid = threadIdx.x;
    const int tb  = blockIdx.x * TT;

    // fold: each thread handles 4 tokens x 4 experts (float4), slabs in order
    {
        const int e4 = tid & 15;          // float4 column
        const int tg = tid >> 4;          // 0..15
#pragma unroll
        for (int r = 0; r < 4; r++) {
            int t = tg * 4 + r;
            const float* p = g_partial + (size_t)(tb + t) * E_EXP + e4 * 4;
            float4 a = *reinterpret_cast<const float4*>(p);
#pragma unroll
            for (int s = 1; s < NSLAB; s++) {
                float4 v = *reinterpret_cast<const float4*>(p + (size_t)s * T_TOK * E_EXP);
                a.x += v.x; a.y += v.y; a.z += v.z; a.w += v.w;
            }
            *reinterpret_cast<float4*>(&lg[t * E_EXP + e4 * 4]) = a;
        }
    }
    __syncthreads();

    // top-8 + softmax: one warp per 8 tokens
    const int w    = tid >> 5;
    const int lane = tid & 31;
    const unsigned FULL = 0xffffffffu;

    for (int s = 0; s < 8; s++) {
        int t = w * 8 + s;
        float v0 = lg[t * E_EXP + lane];
        float v1 = lg[t * E_EXP + 32 + lane];

        float vals[8];
        int   inds[8];
#pragma unroll
        for (int k = 0; k < 8; k++) {
            float bv; int bi;
            if (v0 >= v1) { bv = v0; bi = lane; }
            else          { bv = v1; bi = lane + 32; }
#pragma unroll
            for (int off = 16; off > 0; off >>= 1) {
                float ov = __shfl_xor_sync(FULL, bv, off);
                int   oi = __shfl_xor_sync(FULL, bi, off);
                if (ov > bv || (ov == bv && oi < bi)) { bv = ov; bi = oi; }
            }
            vals[k] = bv;
            inds[k] = bi;
            if (bi == lane)           v0 = -3.4e38f;
            else if (bi == lane + 32) v1 = -3.4e38f;
        }

        if (lane == 0) {
            float m = vals[0];
            float ws[8];
            float ssum = 0.0f;
#pragma unroll
            for (int k = 0; k < 8; k++) { ws[k] = expf(vals[k] - m); ssum += ws[k]; }
            float r = 1.0f / ssum;
            int tg = tb + t;
#pragma unroll
            for (int k = 0; k < 8; k++) {
                out[tg * 8 + k]        = ws[k] * r;
                out[half + tg * 8 + k] = (float)inds[k];
            }
        }
    }
}

extern "C" void kernel_launch(void* const* d_in, const int* in_sizes, int n_in,
                              void* d_out, int out_size) {
    const float* x   = (const float*)d_in[0];
    const float* ker = (const float*)d_in[1];
    float* out = (float*)d_out;
    int half = out_size / 2;

    dim3 grid1(T_TOK / TT, NSLAB);
    slab_gemm_kernel<<<grid1, 64>>>(x, ker);
    fold_topk_kernel<<<T_TOK / TT, 256>>>(out, half);
}

// round 7
// speedup vs baseline: 2.9059x; 1.0733x over previous
#include <cuda_runtime.h>
#include <cstdint>

// Router: logits = x[8192,4096] @ kernel[4096,64]; top-8 per token; softmax over top-8.
// out (fp32): [0 .. T*8) = weights, [T*8 .. 2*T*8) = expert indices (as float)
//
// Physical split-K(8): pass1 computes per-slab partials (sequential fp32, ascending kk
// within the 512-K slab); pass2 folds partials in ascending slab order and does
// top-8 + softmax. Accumulation order replicates the reference — DO NOT CHANGE.

#define T_TOK 8192
#define D_DIM 4096
#define E_EXP 64
#define NSLAB 8
#define SLABK 512
#define TT    64      // tokens per pass1 CTA
#define KC    32      // K-chunk per stage
#define LDK   72      // k-tile row stride (floats), phase-split
#define XTILE (TT * KC)          // 2048 floats
#define KTILE (KC * LDK)         // 2304 floats
#define STAGE (XTILE + KTILE)    // 4352 floats

#define TT2   8       // tokens per pass2 CTA

typedef unsigned long long u64;

__device__ float g_partial[NSLAB * T_TOK * E_EXP];   // 16.8 MB scratch

__device__ __forceinline__ u64 ffma2(u64 a, u64 b, u64 c) {
    u64 d;
    asm("fma.rn.f32x2 %0, %1, %2, %3;" : "=l"(d) : "l"(a), "l"(b), "l"(c));
    return d;
}
__device__ __forceinline__ u64 bcast2(float x) {
    u64 r;
    asm("mov.b64 %0, {%1, %1};" : "=l"(r) : "f"(x));
    return r;
}
__device__ __forceinline__ void cp16(uint32_t smem_addr, const void* gptr) {
    asm volatile("cp.async.cg.shared.global [%0], [%1], 16;" :: "r"(smem_addr), "l"(gptr));
}
__device__ __forceinline__ void cp_commit() { asm volatile("cp.async.commit_group;"); }
__device__ __forceinline__ void cp_wait1()  { asm volatile("cp.async.wait_group 1;"); }
__device__ __forceinline__ void cp_wait0()  { asm volatile("cp.async.wait_group 0;"); }

// ============================ PASS 1: slab GEMM ============================
// grid (128 t-blocks, 8 slabs), 64 threads. Thread tile: 8 rows x 8 experts.
// (unchanged from R6 — proven correct & fast)
__global__ __launch_bounds__(64, 6) void slab_gemm_kernel(
    const float* __restrict__ x,
    const float* __restrict__ ker)
{
    __shared__ float sm[2 * STAGE];   // 34.8 KB

    const int tid  = threadIdx.x;
    const int tx   = tid & 7;            // e-group: e0 = tx*8
    const int ty   = tid >> 3;           // 0..7 -> rows ty + 8*i
    const int e0   = tx * 8;
    const int koff = e0 + ((tx >= 4) ? 4 : 0);
    const int tb   = blockIdx.x * TT;
    const int k0   = blockIdx.y * SLABK;

    const uint32_t smb = (uint32_t)__cvta_generic_to_shared(sm);

    u64 acc[8][4];
#pragma unroll
    for (int i = 0; i < 8; i++)
#pragma unroll
        for (int j = 0; j < 4; j++) acc[i][j] = 0ull;

    auto load_chunk = [&](int c, int s) {
        uint32_t base = smb + (uint32_t)(s * STAGE) * 4u;
#pragma unroll
        for (int j = 0; j < 8; j++) {
            int t = 8 * j + ty;
            uint32_t dst = base + (uint32_t)(t * KC + ((tx ^ ty) << 2)) * 4u;
            const float* src = x + (size_t)(tb + t) * D_DIM + k0 + c * KC + tx * 4;
            cp16(dst, src);
        }
        int e4 = tid & 15;
        int ofs = e4 * 4 + ((e4 >= 8) ? 4 : 0);
#pragma unroll
        for (int j = 0; j < 8; j++) {
            int dk = 4 * j + (tid >> 4);
            uint32_t dst = base + (uint32_t)(XTILE + dk * LDK + ofs) * 4u;
            const float* src = ker + (size_t)(k0 + c * KC + dk) * E_EXP + e4 * 4;
            cp16(dst, src);
        }
        cp_commit();
    };

    load_chunk(0, 0);
    load_chunk(1, 1);

    const int nChunks = SLABK / KC;   // 16
    for (int c = 0; c < nChunks; c++) {
        if (c == nChunks - 1) cp_wait0(); else cp_wait1();
        __syncthreads();

        const int b = c & 1;
        const float* xb_ = sm + b * STAGE;
        const float* kb_ = sm + b * STAGE + XTILE;

#pragma unroll
        for (int c4 = 0; c4 < KC / 4; c4++) {
            const int ch = ((c4 ^ ty) << 2);
            float4 xv[8];
#pragma unroll
            for (int i = 0; i < 8; i++)
                xv[i] = *reinterpret_cast<const float4*>(xb_ + (ty + 8 * i) * KC + ch);
#pragma unroll
            for (int q = 0; q < 4; q++) {
                const int kk = c4 * 4 + q;
                ulonglong2 ka = *reinterpret_cast<const ulonglong2*>(kb_ + kk * LDK + koff);
                ulonglong2 kc = *reinterpret_cast<const ulonglong2*>(kb_ + kk * LDK + koff + 4);
#pragma unroll
                for (int i = 0; i < 8; i++) {
                    float fx = (q == 0) ? xv[i].x : (q == 1) ? xv[i].y
                             : (q == 2) ? xv[i].z : xv[i].w;
                    u64 xp = bcast2(fx);
                    acc[i][0] = ffma2(xp, ka.x, acc[i][0]);
                    acc[i][1] = ffma2(xp, ka.y, acc[i][1]);
                    acc[i][2] = ffma2(xp, kc.x, acc[i][2]);
                    acc[i][3] = ffma2(xp, kc.y, acc[i][3]);
                }
            }
        }
        __syncthreads();
        if (c + 2 < nChunks) load_chunk(c + 2, b);
    }

    float* pout = g_partial + (size_t)blockIdx.y * T_TOK * E_EXP;
#pragma unroll
    for (int i = 0; i < 8; i++) {
        int t = tb + ty + 8 * i;
        float* row = pout + (size_t)t * E_EXP + e0;
        *reinterpret_cast<float4*>(row)     = *reinterpret_cast<float4*>(&acc[i][0]);
        *reinterpret_cast<float4*>(row + 4) = *reinterpret_cast<float4*>(&acc[i][2]);
    }
}

// ====================== PASS 2: fold + top-8 + softmax ======================
// grid = 1024 (8 tokens per CTA), 256 threads: 128 threads fold (one float4 each,
// slabs summed in ascending order), then one warp per token does top-8 + softmax.
__global__ __launch_bounds__(256) void fold_topk_kernel(
    float* __restrict__ out,
    int half)
{
    __shared__ float lg[TT2 * E_EXP];   // 2 KB

    const int tid = threadIdx.x;
    const int tb  = blockIdx.x * TT2;

    // ---- fold: threads 0..127, one (token, e-quad) each; ascending slab order ----
    if (tid < TT2 * (E_EXP / 4)) {
        const int e4 = tid & 15;
        const int t  = tid >> 4;
        const float* p = g_partial + (size_t)(tb + t) * E_EXP + e4 * 4;

        float4 v[NSLAB];
#pragma unroll
        for (int s = 0; s < NSLAB; s++)
            v[s] = *reinterpret_cast<const float4*>(p + (size_t)s * T_TOK * E_EXP);

        float4 a = v[0];
#pragma unroll
        for (int s = 1; s < NSLAB; s++) {
            a.x += v[s].x; a.y += v[s].y; a.z += v[s].z; a.w += v[s].w;
        }
        *reinterpret_cast<float4*>(&lg[t * E_EXP + e4 * 4]) = a;
    }
    __syncthreads();

    // ---- top-8 + softmax: one warp per token ----
    const int w    = tid >> 5;      // token within CTA
    const int lane = tid & 31;
    const unsigned FULL = 0xffffffffu;

    const int t = w;
    float v0 = lg[t * E_EXP + lane];
    float v1 = lg[t * E_EXP + 32 + lane];

    float vals[8];
    int   inds[8];
#pragma unroll
    for (int k = 0; k < 8; k++) {
        float bv; int bi;
        if (v0 >= v1) { bv = v0; bi = lane; }
        else          { bv = v1; bi = lane + 32; }
#pragma unroll
        for (int off = 16; off > 0; off >>= 1) {
            float ov = __shfl_xor_sync(FULL, bv, off);
            int   oi = __shfl_xor_sync(FULL, bi, off);
            if (ov > bv || (ov == bv && oi < bi)) { bv = ov; bi = oi; }
        }
        vals[k] = bv;
        inds[k] = bi;
        if (bi == lane)           v0 = -3.4e38f;
        else if (bi == lane + 32) v1 = -3.4e38f;
    }

    if (lane == 0) {
        float m = vals[0];
        float ws[8];
        float ssum = 0.0f;
#pragma unroll
        for (int k = 0; k < 8; k++) { ws[k] = expf(vals[k] - m); ssum += ws[k]; }
        float r = 1.0f / ssum;
        int tg = tb + t;
#pragma unroll
        for (int k = 0; k < 8; k++) {
            out[tg * 8 + k]        = ws[k] * r;
            out[half + tg * 8 + k] = (float)inds[k];
        }
    }
}

extern "C" void kernel_launch(void* const* d_in, const int* in_sizes, int n_in,
                              void* d_out, int out_size) {
    const float* x   = (const float*)d_in[0];
    const float* ker = (const float*)d_in[1];
    float* out = (float*)d_out;
    int half = out_size / 2;

    dim3 grid1(T_TOK / TT, NSLAB);
    slab_gemm_kernel<<<grid1, 64>>>(x, ker);
    fold_topk_kernel<<<T_TOK / TT2, 256>>>(out, half);
}